// round 10
// baseline (speedup 1.0000x reference)
#include <cuda_runtime.h>
#include <cuda_bf16.h>
#include <math.h>

// GhostVLAD — round 10 (sm_103a). N=32, C=512, P=1024, KG=10, KV=8.
//
// K1a: partial logits. CTA = (32-channel group cc, n); each WARP owns a private
//      128-pixel block and reduces ALL 32 channels over it (no cross-warp
//      reduction, no races). CTA reads a fully contiguous 128KB of x.
//      grid (16,32) x 256 thr.
// K1b: reduce 16 c-groups + bias + softmax -> a[n][k][p], a_sum. grid (4,32).
// K2 : ax GEMM + residual + sumsq partials. grid (16,32).
// K3 : normalize. grid (8,32).

#define N_   32
#define C_   512
#define P_   1024
#define KG_  10
#define KV_  8
#define CCK_ 16                  // channel groups (32 ch each)
#define ACH_ 4                   // a_sum chunks

typedef unsigned long long u64_t;

__device__ __forceinline__ u64_t pack2(float lo, float hi) {
    u64_t r; asm("mov.b64 %0, {%1, %2};" : "=l"(r) : "f"(lo), "f"(hi)); return r;
}
__device__ __forceinline__ void unpack2(u64_t v, float& lo, float& hi) {
    asm("mov.b64 {%0, %1}, %2;" : "=f"(lo), "=f"(hi) : "l"(v));
}
__device__ __forceinline__ void fma2(u64_t& d, u64_t a, u64_t b) {
    asm("fma.rn.f32x2 %0, %1, %2, %0;" : "+l"(d) : "l"(a), "l"(b));
}

// scratch
__device__ u64_t g_plg[5 * CCK_ * N_ * P_];      // 21MB: [kp][cc][n][p]
__device__ float g_a[N_ * KV_ * P_];             // [n][k][p]
__device__ float g_asum[N_ * ACH_ * KV_];        // [n][chunk][k]
__device__ float g_r[N_ * KV_ * C_];             // residuals [n][k][c]
__device__ float g_ss[N_ * KV_ * 16];            // sumsq partials [n][k][cc]

// ---------------- K1a: partial logits, warp-private pixel blocks ----------------
__global__ __launch_bounds__(256, 4) void gv_K1a(
    const float* __restrict__ x, const float* __restrict__ w)
{
    __shared__ u64_t wd[32 * 6];     // 1.5KB: [ci][kp] (pad 6 for 16B-aligned pairs)

    const int cc = blockIdx.x;       // 0..15
    const int n  = blockIdx.y;
    const int t  = threadIdx.x;
    const int wid  = t >> 5;         // pixel block 0..7
    const int lane = t & 31;

    for (int i = t; i < 32 * 5; i += 256) {
        int ci = i / 5, kp = i % 5;
        wd[ci * 6 + kp] = pack2(w[(2 * kp) * C_ + cc * 32 + ci],
                                w[(2 * kp + 1) * C_ + cc * 32 + ci]);
    }
    __syncthreads();

    const int p0 = wid * 128 + lane * 4;     // this thread's 4 pixels
    const float* xb = x + ((size_t)n * C_ + cc * 32) * P_ + p0;

    // acc[kp][px] = (logit_{2kp}, logit_{2kp+1}) for pixel p0+px : 40 regs
    u64_t acc[5][4];
    #pragma unroll
    for (int kp = 0; kp < 5; ++kp)
        #pragma unroll
        for (int px = 0; px < 4; ++px) acc[kp][px] = pack2(0.f, 0.f);

    // march 32 channels; warp LDG.128 = 512B contiguous per channel row
    #pragma unroll 4
    for (int ci = 0; ci < 32; ++ci) {
        const float4 xv = *(const float4*)(xb + (size_t)ci * P_);
        const ulonglong2* wr2 = (const ulonglong2*)(wd + ci * 6);
        ulonglong2 w01 = wr2[0];
        ulonglong2 w23 = wr2[1];
        u64_t w4 = wd[ci * 6 + 4];
        u64_t xd[4];
        xd[0] = pack2(xv.x, xv.x);
        xd[1] = pack2(xv.y, xv.y);
        xd[2] = pack2(xv.z, xv.z);
        xd[3] = pack2(xv.w, xv.w);
        #pragma unroll
        for (int px = 0; px < 4; ++px) {
            fma2(acc[0][px], xd[px], w01.x);
            fma2(acc[1][px], xd[px], w01.y);
            fma2(acc[2][px], xd[px], w23.x);
            fma2(acc[3][px], xd[px], w23.y);
            fma2(acc[4][px], xd[px], w4);
        }
    }

    // warp-private store: per kp, warp writes 1KB contiguous
    #pragma unroll
    for (int kp = 0; kp < 5; ++kp) {
        u64_t* base = g_plg + (((size_t)kp * CCK_ + cc) * N_ + n) * P_ + p0;
        ulonglong2 v01; v01.x = acc[kp][0]; v01.y = acc[kp][1];
        ulonglong2 v23; v23.x = acc[kp][2]; v23.y = acc[kp][3];
        *(ulonglong2*)(base)     = v01;
        *(ulonglong2*)(base + 2) = v23;
    }
}

// ---------------- K1b: reduce + softmax ----------------
__global__ __launch_bounds__(256) void gv_K1b(const float* __restrict__ bias)
{
    __shared__ float asb[8][KV_];
    const int pc = blockIdx.x;          // 0..3
    const int n  = blockIdx.y;
    const int t  = threadIdx.x;
    const int p  = pc * 256 + t;
    const int lane = t & 31, wid = t >> 5;

    float lg[KG_];
    #pragma unroll
    for (int kp = 0; kp < 5; ++kp) {
        float sx = 0.f, sy = 0.f;
        #pragma unroll
        for (int cc = 0; cc < CCK_; ++cc) {
            u64_t v = g_plg[(((size_t)kp * CCK_ + cc) * N_ + n) * P_ + p];
            float lo, hi; unpack2(v, lo, hi);
            sx += lo; sy += hi;
        }
        lg[2 * kp]     = sx + bias[2 * kp];
        lg[2 * kp + 1] = sy + bias[2 * kp + 1];
    }
    float m = lg[0];
    #pragma unroll
    for (int k = 1; k < KG_; ++k) m = fmaxf(m, lg[k]);
    float e[KG_], ssum = 0.f;
    #pragma unroll
    for (int k = 0; k < KG_; ++k) { e[k] = __expf(lg[k] - m); ssum += e[k]; }
    float inv = 1.0f / ssum;

    #pragma unroll
    for (int k = 0; k < KV_; ++k) {
        float a = e[k] * inv;
        g_a[((size_t)n * KV_ + k) * P_ + p] = a;
        float v = a;
        #pragma unroll
        for (int o = 16; o; o >>= 1) v += __shfl_xor_sync(0xffffffffu, v, o);
        if (lane == 0) asb[wid][k] = v;
    }
    __syncthreads();
    if (t < KV_) {
        float v = 0.f;
        #pragma unroll
        for (int wg = 0; wg < 8; ++wg) v += asb[wg][t];
        g_asum[(n * ACH_ + pc) * KV_ + t] = v;
    }
}

// ---------------- K2: ax GEMM + residual + sumsq partials ----------------
__global__ __launch_bounds__(256) void gv_K2(
    const float* __restrict__ x, const float* __restrict__ centers)
{
    __shared__ float a_s[KV_ * P_];     // 32 KB [k][p]
    __shared__ float asum_s[KV_];
    __shared__ float ssb[8][KV_];

    const int cc = blockIdx.x;          // 0..15 (32 channels)
    const int n  = blockIdx.y;
    const int t  = threadIdx.x;
    const int lane = t & 31, wid = t >> 5;

    {
        const float4* ap = (const float4*)(g_a + (size_t)n * KV_ * P_);
        float4* as4 = (float4*)a_s;
        #pragma unroll
        for (int i = 0; i < KV_ * P_ / 4 / 256; ++i)
            as4[t + i * 256] = ap[t + i * 256];
    }
    if (t < KV_) {
        float v = 0.f;
        #pragma unroll
        for (int pc = 0; pc < ACH_; ++pc) v += g_asum[(n * ACH_ + pc) * KV_ + t];
        asum_s[t] = v;
    }
    __syncthreads();

    const int cbase = cc * 32 + wid * 4;
    const float* xb = x + ((size_t)n * C_ + cbase) * P_;

    u64_t acc[4][KV_];
    #pragma unroll
    for (int ch = 0; ch < 4; ++ch)
        #pragma unroll
        for (int k = 0; k < KV_; ++k) acc[ch][k] = pack2(0.f, 0.f);

    #pragma unroll 2
    for (int it = 0; it < 8; ++it) {
        const int p0 = it * 128 + 4 * lane;
        float4 xv[4];
        #pragma unroll
        for (int ch = 0; ch < 4; ++ch)
            xv[ch] = *(const float4*)(xb + (size_t)ch * P_ + p0);
        u64_t a01[KV_], a23[KV_];
        #pragma unroll
        for (int k = 0; k < KV_; ++k) {
            float4 av = *(const float4*)(a_s + k * P_ + p0);
            a01[k] = pack2(av.x, av.y);
            a23[k] = pack2(av.z, av.w);
        }
        #pragma unroll
        for (int ch = 0; ch < 4; ++ch) {
            u64_t x01 = pack2(xv[ch].x, xv[ch].y);
            u64_t x23 = pack2(xv[ch].z, xv[ch].w);
            #pragma unroll
            for (int k = 0; k < KV_; ++k) {
                fma2(acc[ch][k], x01, a01[k]);
                fma2(acc[ch][k], x23, a23[k]);
            }
        }
    }

    float ssq[KV_];
    #pragma unroll
    for (int k = 0; k < KV_; ++k) ssq[k] = 0.f;

    #pragma unroll
    for (int ch = 0; ch < 4; ++ch) {
        #pragma unroll
        for (int k = 0; k < KV_; ++k) {
            float lo, hi; unpack2(acc[ch][k], lo, hi);
            float v = lo + hi;
            #pragma unroll
            for (int o = 16; o; o >>= 1) v += __shfl_xor_sync(0xffffffffu, v, o);
            if (lane == 0) {
                const int c = cbase + ch;
                float r = v - asum_s[k] * centers[k * C_ + c];
                g_r[((size_t)n * KV_ + k) * C_ + c] = r;
                ssq[k] += r * r;
            }
        }
    }
    if (lane == 0) {
        #pragma unroll
        for (int k = 0; k < KV_; ++k) ssb[wid][k] = ssq[k];
    }
    __syncthreads();
    if (t < KV_) {
        float v = 0.f;
        #pragma unroll
        for (int wg = 0; wg < 8; ++wg) v += ssb[wg][t];
        g_ss[((size_t)n * KV_ + t) * 16 + cc] = v;
    }
}

// ---------------- K3: normalize ----------------
__global__ __launch_bounds__(256) void gv_K3(float* __restrict__ out)
{
    const int k = blockIdx.x;
    const int n = blockIdx.y;
    const int t = threadIdx.x;

    float ss = 0.f;
    #pragma unroll
    for (int cc = 0; cc < 16; ++cc) ss += g_ss[((size_t)n * KV_ + k) * 16 + cc];
    float inv = 1.0f / fmaxf(sqrtf(ss), 1e-12f);

    const float* rp = g_r + ((size_t)n * KV_ + k) * C_;
    float* op = out + (size_t)n * (KV_ * C_) + k * C_;
    op[t]       = rp[t]       * inv;
    op[t + 256] = rp[t + 256] * inv;
}

extern "C" void kernel_launch(void* const* d_in, const int* in_sizes, int n_in,
                              void* d_out, int out_size) {
    const float* x       = (const float*)d_in[0];
    const float* conv_w  = (const float*)d_in[1];
    const float* conv_b  = (const float*)d_in[2];
    const float* centers = (const float*)d_in[3];
    float* out = (float*)d_out;

    gv_K1a<<<dim3(CCK_, N_), 256>>>(x, conv_w);
    gv_K1b<<<dim3(ACH_, N_), 256>>>(conv_b);
    gv_K2 <<<dim3(16, N_), 256>>>(x, centers);
    gv_K3 <<<dim3(KV_, N_), 256>>>(out);
}